// round 3
// baseline (speedup 1.0000x reference)
#include <cuda_runtime.h>
#include <cuda_bf16.h>
#include <cstdint>

// Problem constants
#define BQ    4
#define TSEQ  2048
#define CDIM  1024
#define NH    16
#define HD    64
#define MTOT  (BQ * TSEQ)          // 8192 rows
#define QKVF  (3 * CDIM)           // 3072

// Scratch (device globals: no runtime allocation allowed)
__device__ float g_qkv[(size_t)MTOT * QKVF];   // 96 MB
__device__ float g_attn[(size_t)MTOT * CDIM];  // 32 MB

// ---------------------------------------------------------------------------
// SGEMM (NT): C[m,n] = sum_k A[m,k] * B[n,k]
// A: [M,K] row-major, B: [N,K] row-major, C: [M,N] row-major
// 128x128x16 tiles, 256 threads, 8x8 microtile with split-column fragments.
// ---------------------------------------------------------------------------
__global__ __launch_bounds__(256) void sgemm_nt(const float* __restrict__ A,
                                                const float* __restrict__ B,
                                                float* __restrict__ C,
                                                int M, int N, int K)
{
    __shared__ float As[16][128];
    __shared__ float Bs[16][128];

    const int tid = threadIdx.x;
    const int tx  = tid & 15;       // 16 column groups
    const int ty  = tid >> 4;       // 16 row groups
    const int bm  = blockIdx.y * 128;
    const int bn  = blockIdx.x * 128;

    const int lr = tid >> 2;        // 0..63 load row
    const int ls = (tid & 3) * 4;   // k offset of float4

    float acc[8][8];
#pragma unroll
    for (int i = 0; i < 8; i++)
#pragma unroll
        for (int j = 0; j < 8; j++) acc[i][j] = 0.f;

    const float* Ap0 = A + (size_t)(bm + lr)      * K + ls;
    const float* Ap1 = A + (size_t)(bm + lr + 64) * K + ls;
    const float* Bp0 = B + (size_t)(bn + lr)      * K + ls;
    const float* Bp1 = B + (size_t)(bn + lr + 64) * K + ls;

    for (int k0 = 0; k0 < K; k0 += 16) {
        float4 a0 = *(const float4*)(Ap0 + k0);
        float4 a1 = *(const float4*)(Ap1 + k0);
        float4 b0 = *(const float4*)(Bp0 + k0);
        float4 b1 = *(const float4*)(Bp1 + k0);

        __syncthreads();   // previous iteration's compute must be done

        As[ls + 0][lr] = a0.x; As[ls + 1][lr] = a0.y;
        As[ls + 2][lr] = a0.z; As[ls + 3][lr] = a0.w;
        As[ls + 0][lr + 64] = a1.x; As[ls + 1][lr + 64] = a1.y;
        As[ls + 2][lr + 64] = a1.z; As[ls + 3][lr + 64] = a1.w;
        Bs[ls + 0][lr] = b0.x; Bs[ls + 1][lr] = b0.y;
        Bs[ls + 2][lr] = b0.z; Bs[ls + 3][lr] = b0.w;
        Bs[ls + 0][lr + 64] = b1.x; Bs[ls + 1][lr + 64] = b1.y;
        Bs[ls + 2][lr + 64] = b1.z; Bs[ls + 3][lr + 64] = b1.w;

        __syncthreads();

#pragma unroll
        for (int k = 0; k < 16; k++) {
            float4 av0 = *(const float4*)&As[k][ty * 8];
            float4 av1 = *(const float4*)&As[k][ty * 8 + 4];
            float4 bv0 = *(const float4*)&Bs[k][tx * 4];        // cols bn+tx*4..+3
            float4 bv1 = *(const float4*)&Bs[k][tx * 4 + 64];   // cols bn+64+tx*4..+3
            float a_[8] = {av0.x, av0.y, av0.z, av0.w, av1.x, av1.y, av1.z, av1.w};
            float b_[8] = {bv0.x, bv0.y, bv0.z, bv0.w, bv1.x, bv1.y, bv1.z, bv1.w};
#pragma unroll
            for (int i = 0; i < 8; i++)
#pragma unroll
                for (int j = 0; j < 8; j++)
                    acc[i][j] += a_[i] * b_[j];
        }
    }

#pragma unroll
    for (int i = 0; i < 8; i++) {
        float* Cp = C + (size_t)(bm + ty * 8 + i) * N + bn;
        float4 c0 = make_float4(acc[i][0], acc[i][1], acc[i][2], acc[i][3]);
        float4 c1 = make_float4(acc[i][4], acc[i][5], acc[i][6], acc[i][7]);
        *(float4*)&Cp[tx * 4]      = c0;
        *(float4*)&Cp[64 + tx * 4] = c1;
    }
}

// ---------------------------------------------------------------------------
// Flash attention (fp32, causal). One block per (q_tile=64 rows, b, h).
// Tiles of 64x64, d=64. XOR-swizzled smem at float4 granularity:
// float4 (row, d4) lives at word offset row*64 + ((d4 ^ ((row>>2)&7))<<2).
// ---------------------------------------------------------------------------
__device__ __forceinline__ int swz(int r, int d4) {
    return r * 64 + (((d4 ^ ((r >> 2) & 7))) << 2);
}

// smem floats: Qs,Ks,Vs,Ps 4096 each; Ss 64*65; stats 192
#define ATT_SMEM_FLOATS (4 * 4096 + 64 * 65 + 192)
#define ATT_SMEM_BYTES  (ATT_SMEM_FLOATS * 4)

__global__ __launch_bounds__(256) void attn_kernel(const float* __restrict__ qkv,
                                                   float* __restrict__ out)
{
    extern __shared__ float sm[];
    float* Qs   = sm;
    float* Ks   = Qs + 4096;
    float* Vs   = Ks + 4096;
    float* Ps   = Vs + 4096;
    float* Ss   = Ps + 4096;       // [64][65]
    float* m_sm = Ss + 64 * 65;
    float* l_sm = m_sm + 64;
    float* al_sm = l_sm + 64;

    const int tid = threadIdx.x;
    const int qt  = blockIdx.x;          // 0..31
    const int bh  = blockIdx.y;          // 0..63
    const int b   = bh >> 4;
    const int h   = bh & 15;
    const int tx  = tid & 15;
    const int ty  = tid >> 4;

    const size_t base_bt = (size_t)b * TSEQ;

    // Load Q tile (natural [row][d], swizzled)
#pragma unroll
    for (int it = 0; it < 4; it++) {
        int v  = tid + it * 256;      // 0..1023
        int r  = v >> 4;
        int d4 = v & 15;
        const float* p = qkv + (base_bt + qt * 64 + r) * (size_t)QKVF + h * HD + d4 * 4;
        *(float4*)&Qs[swz(r, d4)] = *(const float4*)p;
    }
    if (tid < 64) { m_sm[tid] = -1e30f; l_sm[tid] = 0.f; }

    float o[4][4];
#pragma unroll
    for (int i = 0; i < 4; i++)
#pragma unroll
        for (int c = 0; c < 4; c++) o[i][c] = 0.f;

    for (int kt = 0; kt <= qt; kt++) {
        __syncthreads();   // prior PV reads of Ks/Vs/Ps done; Qs/m/l init done

        // Load K and V tiles
#pragma unroll
        for (int it = 0; it < 4; it++) {
            int v  = tid + it * 256;
            int r  = v >> 4;
            int d4 = v & 15;
            const float* p = qkv + (base_bt + kt * 64 + r) * (size_t)QKVF
                             + CDIM + h * HD + d4 * 4;
            *(float4*)&Ks[swz(r, d4)] = *(const float4*)p;
            *(float4*)&Vs[swz(r, d4)] = *(const float4*)(p + CDIM);
        }
        __syncthreads();

        // S = Q * K^T (4x4 microtile per thread)
        float s_acc[4][4];
#pragma unroll
        for (int i = 0; i < 4; i++)
#pragma unroll
            for (int j = 0; j < 4; j++) s_acc[i][j] = 0.f;

#pragma unroll
        for (int d4 = 0; d4 < 16; d4++) {
            float4 qf[4], kf[4];
#pragma unroll
            for (int i = 0; i < 4; i++) qf[i] = *(const float4*)&Qs[swz(ty * 4 + i, d4)];
#pragma unroll
            for (int j = 0; j < 4; j++) kf[j] = *(const float4*)&Ks[swz(tx * 4 + j, d4)];
#pragma unroll
            for (int i = 0; i < 4; i++)
#pragma unroll
                for (int j = 0; j < 4; j++)
                    s_acc[i][j] += qf[i].x * kf[j].x + qf[i].y * kf[j].y
                                 + qf[i].z * kf[j].z + qf[i].w * kf[j].w;
        }

        // Scale + causal mask, write to Ss
        const int qrow0 = qt * 64 + ty * 4;
        const int kcol0 = kt * 64 + tx * 4;
#pragma unroll
        for (int i = 0; i < 4; i++)
#pragma unroll
            for (int j = 0; j < 4; j++)
                Ss[(ty * 4 + i) * 65 + tx * 4 + j] =
                    (kcol0 + j <= qrow0 + i) ? s_acc[i][j] * 0.125f : -1e30f;
        __syncthreads();

        // Online softmax: 4 threads per row
        {
            int r  = tid >> 2;
            int qq = tid & 3;
            float mo = m_sm[r];
            float tmax = -1e30f;
#pragma unroll
            for (int jj = 0; jj < 16; jj++)
                tmax = fmaxf(tmax, Ss[r * 65 + qq * 16 + jj]);
            tmax = fmaxf(tmax, __shfl_xor_sync(0xffffffffu, tmax, 1));
            tmax = fmaxf(tmax, __shfl_xor_sync(0xffffffffu, tmax, 2));
            float mn = fmaxf(mo, tmax);
            float sum = 0.f;
#pragma unroll
            for (int jj = 0; jj < 16; jj++) {
                int j = qq * 16 + jj;
                float p = __expf(Ss[r * 65 + j] - mn);
                sum += p;
                // Ps[j][r], swizzled
                Ps[swz(j, r >> 2) + (r & 3)] = p;
            }
            sum += __shfl_xor_sync(0xffffffffu, sum, 1);
            sum += __shfl_xor_sync(0xffffffffu, sum, 2);
            if (qq == 0) {
                float alpha = __expf(mo - mn);
                al_sm[r] = alpha;
                m_sm[r]  = mn;
                l_sm[r]  = l_sm[r] * alpha + sum;
            }
        }
        __syncthreads();

        // Rescale O, accumulate O += P * V
        float al[4];
#pragma unroll
        for (int i = 0; i < 4; i++) al[i] = al_sm[ty * 4 + i];
#pragma unroll
        for (int i = 0; i < 4; i++)
#pragma unroll
            for (int c = 0; c < 4; c++) o[i][c] *= al[i];

#pragma unroll 4
        for (int j = 0; j < 64; j++) {
            float4 pf = *(const float4*)&Ps[swz(j, ty)];   // P[j][ty*4..+3]
            float4 vf = *(const float4*)&Vs[swz(j, tx)];   // V[j][tx*4..+3]
            float pa[4] = {pf.x, pf.y, pf.z, pf.w};
            float va[4] = {vf.x, vf.y, vf.z, vf.w};
#pragma unroll
            for (int i = 0; i < 4; i++)
#pragma unroll
                for (int c = 0; c < 4; c++)
                    o[i][c] += pa[i] * va[c];
        }
    }

    // Epilogue: O / l, write [b, t, h*64+d]
#pragma unroll
    for (int i = 0; i < 4; i++) {
        float invl = 1.0f / l_sm[ty * 4 + i];
        float* op = out + (base_bt + qt * 64 + ty * 4 + i) * (size_t)CDIM + h * HD + tx * 4;
        *(float4*)op = make_float4(o[i][0] * invl, o[i][1] * invl,
                                   o[i][2] * invl, o[i][3] * invl);
    }
}

// ---------------------------------------------------------------------------
extern "C" void kernel_launch(void* const* d_in, const int* in_sizes, int n_in,
                              void* d_out, int out_size)
{
    const float* x      = (const float*)d_in[0];
    const float* w_qkv  = (const float*)d_in[1];
    const float* w_proj = (const float*)d_in[2];
    float* out = (float*)d_out;

    float* qkv  = nullptr;
    float* attn = nullptr;
    cudaGetSymbolAddress((void**)&qkv,  g_qkv);
    cudaGetSymbolAddress((void**)&attn, g_attn);

    cudaFuncSetAttribute(attn_kernel,
                         cudaFuncAttributeMaxDynamicSharedMemorySize,
                         ATT_SMEM_BYTES);

    dim3 blk(256);
    // 1) QKV = x @ w_qkv^T   (M=8192, N=3072, K=1024)
    sgemm_nt<<<dim3(QKVF / 128, MTOT / 128), blk>>>(x, w_qkv, qkv, MTOT, QKVF, CDIM);
    // 2) attention
    attn_kernel<<<dim3(TSEQ / 64, BQ * NH), blk, ATT_SMEM_BYTES>>>(qkv, attn);
    // 3) out = attn @ w_proj^T  (M=8192, N=1024, K=1024)
    sgemm_nt<<<dim3(CDIM / 128, MTOT / 128), blk>>>(attn, w_proj, out, MTOT, CDIM, CDIM);
}

// round 5
// speedup vs baseline: 2.3953x; 2.3953x over previous
#include <cuda_runtime.h>
#include <cuda_bf16.h>
#include <cstdint>

// Problem constants
#define BQ    4
#define TSEQ  2048
#define CDIM  1024
#define NH    16
#define HD    64
#define MTOT  (BQ * TSEQ)          // 8192 rows
#define QKVF  (3 * CDIM)           // 3072

// Scratch (device globals: no runtime allocation allowed)
__device__ float g_qkv[(size_t)MTOT * QKVF];   // 96 MB
__device__ float g_attn[(size_t)MTOT * CDIM];  // 32 MB

// ---------------------------------------------------------------------------
// TF32 tensor-core GEMM (NT): C[m,n] = sum_k A[m,k] * B[n,k]
// A: [M,K] row-major, B: [N,K] row-major, C: [M,N] row-major.
// 128x128x16 block tiles, 256 threads = 8 warps (2 n x 4 m), warp tile 32x64
// as 2x8 mma.sync.m16n8k8 tiles. fp32 accumulation.
// Smem rows stride 20 words: fragment LDS provably conflict-free
// (banks 20j+c mod 32, j=0..7 tile all 32 banks), STS.128 at worst 2-way.
// ---------------------------------------------------------------------------
#define SSTRIDE 20

__device__ __forceinline__ uint32_t f2tf(float f) {
    uint32_t u;
    asm("cvt.rna.tf32.f32 %0, %1;" : "=r"(u) : "f"(f));
    return u;
}

__global__ __launch_bounds__(256, 2) void gemm_tf32_nt(const float* __restrict__ A,
                                                       const float* __restrict__ B,
                                                       float* __restrict__ C,
                                                       int M, int N, int K)
{
    __shared__ __align__(16) uint32_t As[2][128 * SSTRIDE];
    __shared__ __align__(16) uint32_t Bs[2][128 * SSTRIDE];

    const int tid  = threadIdx.x;
    const int bm   = blockIdx.y * 128;
    const int bn   = blockIdx.x * 128;
    const int warp = tid >> 5;
    const int lane = tid & 31;
    const int r    = lane >> 2;      // fragment row group 0..7
    const int c    = lane & 3;       // fragment col group 0..3
    const int wm   = (warp >> 1) * 32;
    const int wn   = (warp & 1) * 64;

    // Loader mapping: float4 along k, coalesced in gmem
    const int lr = tid >> 2;         // 0..63 (rows lr and lr+64)
    const int ls = (tid & 3) * 4;    // k offset

    const float* Ap0 = A + (size_t)(bm + lr)      * K + ls;
    const float* Ap1 = A + (size_t)(bm + lr + 64) * K + ls;
    const float* Bp0 = B + (size_t)(bn + lr)      * K + ls;
    const float* Bp1 = B + (size_t)(bn + lr + 64) * K + ls;

    float acc[2][8][4];
#pragma unroll
    for (int mi = 0; mi < 2; mi++)
#pragma unroll
        for (int ni = 0; ni < 8; ni++)
#pragma unroll
            for (int e = 0; e < 4; e++) acc[mi][ni][e] = 0.f;

    auto stash = [&](int buf, float4 va0, float4 va1, float4 vb0, float4 vb1) {
        uint4 u;
        u.x = f2tf(va0.x); u.y = f2tf(va0.y); u.z = f2tf(va0.z); u.w = f2tf(va0.w);
        *(uint4*)&As[buf][lr * SSTRIDE + ls] = u;
        u.x = f2tf(va1.x); u.y = f2tf(va1.y); u.z = f2tf(va1.z); u.w = f2tf(va1.w);
        *(uint4*)&As[buf][(lr + 64) * SSTRIDE + ls] = u;
        u.x = f2tf(vb0.x); u.y = f2tf(vb0.y); u.z = f2tf(vb0.z); u.w = f2tf(vb0.w);
        *(uint4*)&Bs[buf][lr * SSTRIDE + ls] = u;
        u.x = f2tf(vb1.x); u.y = f2tf(vb1.y); u.z = f2tf(vb1.z); u.w = f2tf(vb1.w);
        *(uint4*)&Bs[buf][(lr + 64) * SSTRIDE + ls] = u;
    };

    // Prologue: tile 0 into buffer 0
    {
        float4 a0 = *(const float4*)(Ap0);
        float4 a1 = *(const float4*)(Ap1);
        float4 b0 = *(const float4*)(Bp0);
        float4 b1 = *(const float4*)(Bp1);
        stash(0, a0, a1, b0, b1);
    }
    __syncthreads();

    const int NT = K / 16;
    int p = 0;
    for (int kt = 0; kt < NT; kt++) {
        float4 na0, na1, nb0, nb1;
        const bool has_next = (kt + 1 < NT);
        if (has_next) {
            const int off = (kt + 1) * 16;
            na0 = *(const float4*)(Ap0 + off);
            na1 = *(const float4*)(Ap1 + off);
            nb0 = *(const float4*)(Bp0 + off);
            nb1 = *(const float4*)(Bp1 + off);
        }

        // Compute on buffer p
#pragma unroll
        for (int ks = 0; ks < 16; ks += 8) {
            uint32_t af[2][4];
#pragma unroll
            for (int mi = 0; mi < 2; mi++) {
                const uint32_t* base = &As[p][(wm + mi * 16 + r) * SSTRIDE];
                af[mi][0] = base[ks + c];
                af[mi][1] = base[8 * SSTRIDE + ks + c];
                af[mi][2] = base[ks + c + 4];
                af[mi][3] = base[8 * SSTRIDE + ks + c + 4];
            }
            uint32_t bf[8][2];
#pragma unroll
            for (int ni = 0; ni < 8; ni++) {
                const uint32_t* base = &Bs[p][(wn + ni * 8 + r) * SSTRIDE];
                bf[ni][0] = base[ks + c];
                bf[ni][1] = base[ks + c + 4];
            }
#pragma unroll
            for (int mi = 0; mi < 2; mi++)
#pragma unroll
                for (int ni = 0; ni < 8; ni++) {
                    float* d = acc[mi][ni];
                    asm volatile(
                        "mma.sync.aligned.m16n8k8.row.col.f32.tf32.tf32.f32 "
                        "{%0,%1,%2,%3}, {%4,%5,%6,%7}, {%8,%9}, {%0,%1,%2,%3};"
                        : "+f"(d[0]), "+f"(d[1]), "+f"(d[2]), "+f"(d[3])
                        : "r"(af[mi][0]), "r"(af[mi][1]), "r"(af[mi][2]), "r"(af[mi][3]),
                          "r"(bf[ni][0]), "r"(bf[ni][1]));
                }
        }

        if (has_next) {
            stash(p ^ 1, na0, na1, nb0, nb1);
            __syncthreads();
            p ^= 1;
        }
    }

    // Epilogue: fragment (row, 2c) / (row+8, 2c) float2 stores
#pragma unroll
    for (int mi = 0; mi < 2; mi++) {
        const int row0 = bm + wm + mi * 16 + r;
#pragma unroll
        for (int ni = 0; ni < 8; ni++) {
            const int col = bn + wn + ni * 8 + 2 * c;
            float* d = acc[mi][ni];
            *(float2*)&C[(size_t)row0 * N + col]       = make_float2(d[0], d[1]);
            *(float2*)&C[(size_t)(row0 + 8) * N + col] = make_float2(d[2], d[3]);
        }
    }
}

// ---------------------------------------------------------------------------
// Flash attention (fp32, causal). One block per (q_tile=64 rows, b, h).
// Tiles of 64x64, d=64. XOR-swizzled smem at float4 granularity.
// ---------------------------------------------------------------------------
__device__ __forceinline__ int swz(int r, int d4) {
    return r * 64 + (((d4 ^ ((r >> 2) & 7))) << 2);
}

#define ATT_SMEM_FLOATS (4 * 4096 + 64 * 65 + 192)
#define ATT_SMEM_BYTES  (ATT_SMEM_FLOATS * 4)

__global__ __launch_bounds__(256) void attn_kernel(const float* __restrict__ qkv,
                                                   float* __restrict__ out)
{
    extern __shared__ float sm[];
    float* Qs   = sm;
    float* Ks   = Qs + 4096;
    float* Vs   = Ks + 4096;
    float* Ps   = Vs + 4096;
    float* Ss   = Ps + 4096;       // [64][65]
    float* m_sm = Ss + 64 * 65;
    float* l_sm = m_sm + 64;
    float* al_sm = l_sm + 64;

    const int tid = threadIdx.x;
    const int qt  = blockIdx.x;          // 0..31
    const int bh  = blockIdx.y;          // 0..63
    const int b   = bh >> 4;
    const int h   = bh & 15;
    const int tx  = tid & 15;
    const int ty  = tid >> 4;

    const size_t base_bt = (size_t)b * TSEQ;

#pragma unroll
    for (int it = 0; it < 4; it++) {
        int v  = tid + it * 256;
        int r  = v >> 4;
        int d4 = v & 15;
        const float* p = qkv + (base_bt + qt * 64 + r) * (size_t)QKVF + h * HD + d4 * 4;
        *(float4*)&Qs[swz(r, d4)] = *(const float4*)p;
    }
    if (tid < 64) { m_sm[tid] = -1e30f; l_sm[tid] = 0.f; }

    float o[4][4];
#pragma unroll
    for (int i = 0; i < 4; i++)
#pragma unroll
        for (int c = 0; c < 4; c++) o[i][c] = 0.f;

    for (int kt = 0; kt <= qt; kt++) {
        __syncthreads();

#pragma unroll
        for (int it = 0; it < 4; it++) {
            int v  = tid + it * 256;
            int r  = v >> 4;
            int d4 = v & 15;
            const float* p = qkv + (base_bt + kt * 64 + r) * (size_t)QKVF
                             + CDIM + h * HD + d4 * 4;
            *(float4*)&Ks[swz(r, d4)] = *(const float4*)p;
            *(float4*)&Vs[swz(r, d4)] = *(const float4*)(p + CDIM);
        }
        __syncthreads();

        float s_acc[4][4];
#pragma unroll
        for (int i = 0; i < 4; i++)
#pragma unroll
            for (int j = 0; j < 4; j++) s_acc[i][j] = 0.f;

#pragma unroll
        for (int d4 = 0; d4 < 16; d4++) {
            float4 qf[4], kf[4];
#pragma unroll
            for (int i = 0; i < 4; i++) qf[i] = *(const float4*)&Qs[swz(ty * 4 + i, d4)];
#pragma unroll
            for (int j = 0; j < 4; j++) kf[j] = *(const float4*)&Ks[swz(tx * 4 + j, d4)];
#pragma unroll
            for (int i = 0; i < 4; i++)
#pragma unroll
                for (int j = 0; j < 4; j++)
                    s_acc[i][j] += qf[i].x * kf[j].x + qf[i].y * kf[j].y
                                 + qf[i].z * kf[j].z + qf[i].w * kf[j].w;
        }

        const int qrow0 = qt * 64 + ty * 4;
        const int kcol0 = kt * 64 + tx * 4;
#pragma unroll
        for (int i = 0; i < 4; i++)
#pragma unroll
            for (int j = 0; j < 4; j++)
                Ss[(ty * 4 + i) * 65 + tx * 4 + j] =
                    (kcol0 + j <= qrow0 + i) ? s_acc[i][j] * 0.125f : -1e30f;
        __syncthreads();

        {
            int r  = tid >> 2;
            int qq = tid & 3;
            float mo = m_sm[r];
            float tmax = -1e30f;
#pragma unroll
            for (int jj = 0; jj < 16; jj++)
                tmax = fmaxf(tmax, Ss[r * 65 + qq * 16 + jj]);
            tmax = fmaxf(tmax, __shfl_xor_sync(0xffffffffu, tmax, 1));
            tmax = fmaxf(tmax, __shfl_xor_sync(0xffffffffu, tmax, 2));
            float mn = fmaxf(mo, tmax);
            float sum = 0.f;
#pragma unroll
            for (int jj = 0; jj < 16; jj++) {
                int j = qq * 16 + jj;
                float p = __expf(Ss[r * 65 + j] - mn);
                sum += p;
                Ps[swz(j, r >> 2) + (r & 3)] = p;
            }
            sum += __shfl_xor_sync(0xffffffffu, sum, 1);
            sum += __shfl_xor_sync(0xffffffffu, sum, 2);
            if (qq == 0) {
                float alpha = __expf(mo - mn);
                al_sm[r] = alpha;
                m_sm[r]  = mn;
                l_sm[r]  = l_sm[r] * alpha + sum;
            }
        }
        __syncthreads();

        float al[4];
#pragma unroll
        for (int i = 0; i < 4; i++) al[i] = al_sm[ty * 4 + i];
#pragma unroll
        for (int i = 0; i < 4; i++)
#pragma unroll
            for (int c = 0; c < 4; c++) o[i][c] *= al[i];

#pragma unroll 4
        for (int j = 0; j < 64; j++) {
            float4 pf = *(const float4*)&Ps[swz(j, ty)];
            float4 vf = *(const float4*)&Vs[swz(j, tx)];
            float pa[4] = {pf.x, pf.y, pf.z, pf.w};
            float va[4] = {vf.x, vf.y, vf.z, vf.w};
#pragma unroll
            for (int i = 0; i < 4; i++)
#pragma unroll
                for (int c = 0; c < 4; c++)
                    o[i][c] += pa[i] * va[c];
        }
    }

#pragma unroll
    for (int i = 0; i < 4; i++) {
        float invl = 1.0f / l_sm[ty * 4 + i];
        float* op = out + (base_bt + qt * 64 + ty * 4 + i) * (size_t)CDIM + h * HD + tx * 4;
        *(float4*)op = make_float4(o[i][0] * invl, o[i][1] * invl,
                                   o[i][2] * invl, o[i][3] * invl);
    }
}

// ---------------------------------------------------------------------------
extern "C" void kernel_launch(void* const* d_in, const int* in_sizes, int n_in,
                              void* d_out, int out_size)
{
    const float* x      = (const float*)d_in[0];
    const float* w_qkv  = (const float*)d_in[1];
    const float* w_proj = (const float*)d_in[2];
    float* out = (float*)d_out;

    float* qkv  = nullptr;
    float* attn = nullptr;
    cudaGetSymbolAddress((void**)&qkv,  g_qkv);
    cudaGetSymbolAddress((void**)&attn, g_attn);

    cudaFuncSetAttribute(attn_kernel,
                         cudaFuncAttributeMaxDynamicSharedMemorySize,
                         ATT_SMEM_BYTES);

    dim3 blk(256);
    // 1) QKV = x @ w_qkv^T   (M=8192, N=3072, K=1024)  -- TF32 tensor cores
    gemm_tf32_nt<<<dim3(QKVF / 128, MTOT / 128), blk>>>(x, w_qkv, qkv, MTOT, QKVF, CDIM);
    // 2) attention (fp32 SIMT, unchanged this round)
    attn_kernel<<<dim3(TSEQ / 64, BQ * NH), blk, ATT_SMEM_BYTES>>>(qkv, attn);
    // 3) out = attn @ w_proj^T  (M=8192, N=1024, K=1024) -- TF32 tensor cores
    gemm_tf32_nt<<<dim3(CDIM / 128, MTOT / 128), blk>>>(attn, w_proj, out, MTOT, CDIM, CDIM);
}

// round 7
// speedup vs baseline: 5.0697x; 2.1165x over previous
#include <cuda_runtime.h>
#include <cuda_bf16.h>
#include <cstdint>

// Problem constants
#define BQ    4
#define TSEQ  2048
#define CDIM  1024
#define NH    16
#define HD    64
#define MTOT  (BQ * TSEQ)          // 8192 rows
#define QKVF  (3 * CDIM)           // 3072

// Scratch (device globals: no runtime allocation allowed)
__device__ float g_qkv[(size_t)MTOT * QKVF];   // 96 MB
__device__ float g_attn[(size_t)MTOT * CDIM];  // 32 MB

__device__ __forceinline__ uint32_t f2tf(float f) {
    uint32_t u;
    asm("cvt.rna.tf32.f32 %0, %1;" : "=r"(u) : "f"(f));
    return u;
}

// ---------------------------------------------------------------------------
// TF32 tensor-core GEMM (NT): C[m,n] = sum_k A[m,k] * B[n,k]   (unchanged R4)
// ---------------------------------------------------------------------------
#define SSTRIDE 20

__global__ __launch_bounds__(256, 2) void gemm_tf32_nt(const float* __restrict__ A,
                                                       const float* __restrict__ B,
                                                       float* __restrict__ C,
                                                       int M, int N, int K)
{
    __shared__ __align__(16) uint32_t As[2][128 * SSTRIDE];
    __shared__ __align__(16) uint32_t Bs[2][128 * SSTRIDE];

    const int tid  = threadIdx.x;
    const int bm   = blockIdx.y * 128;
    const int bn   = blockIdx.x * 128;
    const int warp = tid >> 5;
    const int lane = tid & 31;
    const int r    = lane >> 2;
    const int c    = lane & 3;
    const int wm   = (warp >> 1) * 32;
    const int wn   = (warp & 1) * 64;

    const int lr = tid >> 2;
    const int ls = (tid & 3) * 4;

    const float* Ap0 = A + (size_t)(bm + lr)      * K + ls;
    const float* Ap1 = A + (size_t)(bm + lr + 64) * K + ls;
    const float* Bp0 = B + (size_t)(bn + lr)      * K + ls;
    const float* Bp1 = B + (size_t)(bn + lr + 64) * K + ls;

    float acc[2][8][4];
#pragma unroll
    for (int mi = 0; mi < 2; mi++)
#pragma unroll
        for (int ni = 0; ni < 8; ni++)
#pragma unroll
            for (int e = 0; e < 4; e++) acc[mi][ni][e] = 0.f;

    auto stash = [&](int buf, float4 va0, float4 va1, float4 vb0, float4 vb1) {
        uint4 u;
        u.x = f2tf(va0.x); u.y = f2tf(va0.y); u.z = f2tf(va0.z); u.w = f2tf(va0.w);
        *(uint4*)&As[buf][lr * SSTRIDE + ls] = u;
        u.x = f2tf(va1.x); u.y = f2tf(va1.y); u.z = f2tf(va1.z); u.w = f2tf(va1.w);
        *(uint4*)&As[buf][(lr + 64) * SSTRIDE + ls] = u;
        u.x = f2tf(vb0.x); u.y = f2tf(vb0.y); u.z = f2tf(vb0.z); u.w = f2tf(vb0.w);
        *(uint4*)&Bs[buf][lr * SSTRIDE + ls] = u;
        u.x = f2tf(vb1.x); u.y = f2tf(vb1.y); u.z = f2tf(vb1.z); u.w = f2tf(vb1.w);
        *(uint4*)&Bs[buf][(lr + 64) * SSTRIDE + ls] = u;
    };

    {
        float4 a0 = *(const float4*)(Ap0);
        float4 a1 = *(const float4*)(Ap1);
        float4 b0 = *(const float4*)(Bp0);
        float4 b1 = *(const float4*)(Bp1);
        stash(0, a0, a1, b0, b1);
    }
    __syncthreads();

    const int NT = K / 16;
    int p = 0;
    for (int kt = 0; kt < NT; kt++) {
        float4 na0, na1, nb0, nb1;
        const bool has_next = (kt + 1 < NT);
        if (has_next) {
            const int off = (kt + 1) * 16;
            na0 = *(const float4*)(Ap0 + off);
            na1 = *(const float4*)(Ap1 + off);
            nb0 = *(const float4*)(Bp0 + off);
            nb1 = *(const float4*)(Bp1 + off);
        }

#pragma unroll
        for (int ks = 0; ks < 16; ks += 8) {
            uint32_t af[2][4];
#pragma unroll
            for (int mi = 0; mi < 2; mi++) {
                const uint32_t* base = &As[p][(wm + mi * 16 + r) * SSTRIDE];
                af[mi][0] = base[ks + c];
                af[mi][1] = base[8 * SSTRIDE + ks + c];
                af[mi][2] = base[ks + c + 4];
                af[mi][3] = base[8 * SSTRIDE + ks + c + 4];
            }
            uint32_t bf[8][2];
#pragma unroll
            for (int ni = 0; ni < 8; ni++) {
                const uint32_t* base = &Bs[p][(wn + ni * 8 + r) * SSTRIDE];
                bf[ni][0] = base[ks + c];
                bf[ni][1] = base[ks + c + 4];
            }
#pragma unroll
            for (int mi = 0; mi < 2; mi++)
#pragma unroll
                for (int ni = 0; ni < 8; ni++) {
                    float* d = acc[mi][ni];
                    asm volatile(
                        "mma.sync.aligned.m16n8k8.row.col.f32.tf32.tf32.f32 "
                        "{%0,%1,%2,%3}, {%4,%5,%6,%7}, {%8,%9}, {%0,%1,%2,%3};"
                        : "+f"(d[0]), "+f"(d[1]), "+f"(d[2]), "+f"(d[3])
                        : "r"(af[mi][0]), "r"(af[mi][1]), "r"(af[mi][2]), "r"(af[mi][3]),
                          "r"(bf[ni][0]), "r"(bf[ni][1]));
                }
        }

        if (has_next) {
            stash(p ^ 1, na0, na1, nb0, nb1);
            __syncthreads();
            p ^= 1;
        }
    }

#pragma unroll
    for (int mi = 0; mi < 2; mi++) {
        const int row0 = bm + wm + mi * 16 + r;
#pragma unroll
        for (int ni = 0; ni < 8; ni++) {
            const int col = bn + wn + ni * 8 + 2 * c;
            float* d = acc[mi][ni];
            *(float2*)&C[(size_t)row0 * N + col]       = make_float2(d[0], d[1]);
            *(float2*)&C[(size_t)(row0 + 8) * N + col] = make_float2(d[2], d[3]);
        }
    }
}

// ---------------------------------------------------------------------------
// Tensor-core flash attention (tf32 mma, fp32 accum, causal).
// Block: 128 q-rows, 8 warps (16 rows each). K/V tiles 64 x 64.
// Q fragments + O accumulators + softmax stats fully register-resident.
// P staged per-warp through smem to re-shape accumulator->A fragment.
// Strides: Ks/Ps 68 (frag LDS conflict-free), Vs 72 (B-frag conflict-free).
// ---------------------------------------------------------------------------
#define KSTR 68
#define VSTR 72
#define PSTR 68
#define ATT_SMEM_WORDS (64 * KSTR + 64 * VSTR + 128 * PSTR)
#define ATT_SMEM_BYTES (ATT_SMEM_WORDS * 4)

__global__ __launch_bounds__(256, 2) void attn_tc(const float* __restrict__ qkv,
                                                  float* __restrict__ out)
{
    extern __shared__ uint32_t smu[];
    uint32_t* Ks = smu;                 // [64][KSTR]  tf32 bits
    uint32_t* Vs = Ks + 64 * KSTR;      // [64][VSTR]  tf32 bits
    uint32_t* Ps = Vs + 64 * VSTR;      // [128][PSTR] fp32 bits (Q stage) / tf32 bits (P)

    const int tid  = threadIdx.x;
    const int warp = tid >> 5;
    const int lane = tid & 31;
    const int r    = lane >> 2;       // fragment row group 0..7
    const int c    = lane & 3;        // fragment col group 0..3
    const int qt   = blockIdx.x;      // 0..15
    const int bh   = blockIdx.y;      // 0..63
    const int b    = bh >> 4;
    const int h    = bh & 15;
    const int wrow = warp * 16;
    const size_t base = (size_t)b * TSEQ;

    // ---- Stage Q (pre-scaled by 1/8) into Ps as fp32 bits ----
#pragma unroll
    for (int it = 0; it < 8; it++) {
        int idx = tid + it * 256;        // 0..2047
        int row = idx >> 4;
        int d4  = idx & 15;
        float4 v = *(const float4*)(qkv + (base + qt * 128 + row) * (size_t)QKVF
                                    + h * HD + d4 * 4);
        uint4 u;
        u.x = __float_as_uint(v.x * 0.125f);
        u.y = __float_as_uint(v.y * 0.125f);
        u.z = __float_as_uint(v.z * 0.125f);
        u.w = __float_as_uint(v.w * 0.125f);
        *(uint4*)&Ps[row * PSTR + d4 * 4] = u;
    }
    __syncthreads();

    // ---- Q fragments (registers, reused for all k-tiles) ----
    uint32_t qf[8][4];
#pragma unroll
    for (int k0 = 0; k0 < 8; k0++) {
        const uint32_t* bq = &Ps[(wrow + r) * PSTR + k0 * 8];
        qf[k0][0] = f2tf(__uint_as_float(bq[c]));
        qf[k0][1] = f2tf(__uint_as_float(bq[8 * PSTR + c]));
        qf[k0][2] = f2tf(__uint_as_float(bq[c + 4]));
        qf[k0][3] = f2tf(__uint_as_float(bq[8 * PSTR + c + 4]));
    }

    float o[8][4];
#pragma unroll
    for (int ni = 0; ni < 8; ni++)
#pragma unroll
        for (int e = 0; e < 4; e++) o[ni][e] = 0.f;
    float m0 = -1e30f, m1 = -1e30f, l0 = 0.f, l1 = 0.f;

    const int ktmax = 2 * qt + 1;
    for (int kt = 0; kt <= ktmax; kt++) {
        __syncthreads();   // prior iter done reading Ks/Vs; Q-frag reads done (kt=0)

        // ---- Load K, V tiles (tf32 converted at store) ----
#pragma unroll
        for (int it = 0; it < 4; it++) {
            int idx = tid + it * 256;    // 0..1023
            int row = idx >> 4;
            int d4  = idx & 15;
            const float* p = qkv + (base + kt * 64 + row) * (size_t)QKVF
                             + CDIM + h * HD + d4 * 4;
            float4 kv = *(const float4*)p;
            float4 vv = *(const float4*)(p + CDIM);
            uint4 u;
            u.x = f2tf(kv.x); u.y = f2tf(kv.y); u.z = f2tf(kv.z); u.w = f2tf(kv.w);
            *(uint4*)&Ks[row * KSTR + d4 * 4] = u;
            u.x = f2tf(vv.x); u.y = f2tf(vv.y); u.z = f2tf(vv.z); u.w = f2tf(vv.w);
            *(uint4*)&Vs[row * VSTR + d4 * 4] = u;
        }
        __syncthreads();

        // ---- S = Q * K^T (scaled), warp computes 16 x 64 ----
        float s[8][4];
#pragma unroll
        for (int ni = 0; ni < 8; ni++)
#pragma unroll
            for (int e = 0; e < 4; e++) s[ni][e] = 0.f;

#pragma unroll
        for (int k0 = 0; k0 < 8; k0++) {
#pragma unroll
            for (int ni = 0; ni < 8; ni++) {
                const uint32_t* bk = &Ks[(ni * 8 + r) * KSTR + k0 * 8];
                uint32_t b0 = bk[c];
                uint32_t b1 = bk[c + 4];
                float* d = s[ni];
                asm volatile(
                    "mma.sync.aligned.m16n8k8.row.col.f32.tf32.tf32.f32 "
                    "{%0,%1,%2,%3}, {%4,%5,%6,%7}, {%8,%9}, {%0,%1,%2,%3};"
                    : "+f"(d[0]), "+f"(d[1]), "+f"(d[2]), "+f"(d[3])
                    : "r"(qf[k0][0]), "r"(qf[k0][1]), "r"(qf[k0][2]), "r"(qf[k0][3]),
                      "r"(b0), "r"(b1));
            }
        }

        // ---- Causal mask (only the last two k-tiles can clip) ----
        if (kt >= 2 * qt) {
            const int row0 = qt * 128 + wrow + r;
#pragma unroll
            for (int ni = 0; ni < 8; ni++) {
                int col = kt * 64 + ni * 8 + 2 * c;
                if (col     > row0)     s[ni][0] = -1e30f;
                if (col + 1 > row0)     s[ni][1] = -1e30f;
                if (col     > row0 + 8) s[ni][2] = -1e30f;
                if (col + 1 > row0 + 8) s[ni][3] = -1e30f;
            }
        }

        // ---- Online softmax (rows r and r+8; 4 lanes per row) ----
        float mx0 = -1e30f, mx1 = -1e30f;
#pragma unroll
        for (int ni = 0; ni < 8; ni++) {
            mx0 = fmaxf(mx0, fmaxf(s[ni][0], s[ni][1]));
            mx1 = fmaxf(mx1, fmaxf(s[ni][2], s[ni][3]));
        }
        mx0 = fmaxf(mx0, __shfl_xor_sync(0xffffffffu, mx0, 1));
        mx0 = fmaxf(mx0, __shfl_xor_sync(0xffffffffu, mx0, 2));
        mx1 = fmaxf(mx1, __shfl_xor_sync(0xffffffffu, mx1, 1));
        mx1 = fmaxf(mx1, __shfl_xor_sync(0xffffffffu, mx1, 2));

        float mn0 = fmaxf(m0, mx0);
        float mn1 = fmaxf(m1, mx1);
        float a0 = __expf(m0 - mn0);
        float a1 = __expf(m1 - mn1);
        m0 = mn0; m1 = mn1;

        float sum0 = 0.f, sum1 = 0.f;
#pragma unroll
        for (int ni = 0; ni < 8; ni++) {
            s[ni][0] = __expf(s[ni][0] - mn0);
            s[ni][1] = __expf(s[ni][1] - mn0);
            s[ni][2] = __expf(s[ni][2] - mn1);
            s[ni][3] = __expf(s[ni][3] - mn1);
            sum0 += s[ni][0] + s[ni][1];
            sum1 += s[ni][2] + s[ni][3];
        }
        sum0 += __shfl_xor_sync(0xffffffffu, sum0, 1);
        sum0 += __shfl_xor_sync(0xffffffffu, sum0, 2);
        sum1 += __shfl_xor_sync(0xffffffffu, sum1, 1);
        sum1 += __shfl_xor_sync(0xffffffffu, sum1, 2);
        l0 = l0 * a0 + sum0;
        l1 = l1 * a1 + sum1;

        // rescale O
#pragma unroll
        for (int ni = 0; ni < 8; ni++) {
            o[ni][0] *= a0; o[ni][1] *= a0;
            o[ni][2] *= a1; o[ni][3] *= a1;
        }

        // ---- Store P (tf32 bits) to per-warp smem region ----
#pragma unroll
        for (int ni = 0; ni < 8; ni++) {
            uint2 u;
            u.x = f2tf(s[ni][0]); u.y = f2tf(s[ni][1]);
            *(uint2*)&Ps[(wrow + r) * PSTR + ni * 8 + 2 * c] = u;
            u.x = f2tf(s[ni][2]); u.y = f2tf(s[ni][3]);
            *(uint2*)&Ps[(wrow + r + 8) * PSTR + ni * 8 + 2 * c] = u;
        }
        __syncwarp();

        // ---- O += P * V ----
#pragma unroll
        for (int k0 = 0; k0 < 8; k0++) {
            const uint32_t* pb = &Ps[(wrow + r) * PSTR + k0 * 8];
            uint32_t pa0 = pb[c];
            uint32_t pa1 = pb[8 * PSTR + c];
            uint32_t pa2 = pb[c + 4];
            uint32_t pa3 = pb[8 * PSTR + c + 4];
#pragma unroll
            for (int ni = 0; ni < 8; ni++) {
                uint32_t b0 = Vs[(k0 * 8 + c) * VSTR + ni * 8 + r];
                uint32_t b1 = Vs[(k0 * 8 + c + 4) * VSTR + ni * 8 + r];
                float* d = o[ni];
                asm volatile(
                    "mma.sync.aligned.m16n8k8.row.col.f32.tf32.tf32.f32 "
                    "{%0,%1,%2,%3}, {%4,%5,%6,%7}, {%8,%9}, {%0,%1,%2,%3};"
                    : "+f"(d[0]), "+f"(d[1]), "+f"(d[2]), "+f"(d[3])
                    : "r"(pa0), "r"(pa1), "r"(pa2), "r"(pa3),
                      "r"(b0), "r"(b1));
            }
        }
    }

    // ---- Epilogue: O / l, write [b, t, h*64 + d] ----
    const float inv0 = 1.0f / l0;
    const float inv1 = 1.0f / l1;
    const size_t row0 = base + qt * 128 + wrow + r;
#pragma unroll
    for (int ni = 0; ni < 8; ni++) {
        const int col = h * HD + ni * 8 + 2 * c;
        *(float2*)&out[row0 * CDIM + col] =
            make_float2(o[ni][0] * inv0, o[ni][1] * inv0);
        *(float2*)&out[(row0 + 8) * CDIM + col] =
            make_float2(o[ni][2] * inv1, o[ni][3] * inv1);
    }
}

// ---------------------------------------------------------------------------
extern "C" void kernel_launch(void* const* d_in, const int* in_sizes, int n_in,
                              void* d_out, int out_size)
{
    const float* x      = (const float*)d_in[0];
    const float* w_qkv  = (const float*)d_in[1];
    const float* w_proj = (const float*)d_in[2];
    float* out = (float*)d_out;

    float* qkv  = nullptr;
    float* attn = nullptr;
    cudaGetSymbolAddress((void**)&qkv,  g_qkv);
    cudaGetSymbolAddress((void**)&attn, g_attn);

    cudaFuncSetAttribute(attn_tc,
                         cudaFuncAttributeMaxDynamicSharedMemorySize,
                         ATT_SMEM_BYTES);

    dim3 blk(256);
    // 1) QKV = x @ w_qkv^T   (M=8192, N=3072, K=1024)  -- tf32 mma
    gemm_tf32_nt<<<dim3(QKVF / 128, MTOT / 128), blk>>>(x, w_qkv, qkv, MTOT, QKVF, CDIM);
    // 2) attention -- tf32 mma flash attention
    attn_tc<<<dim3(TSEQ / 128, BQ * NH), blk, ATT_SMEM_BYTES>>>(qkv, attn);
    // 3) out = attn @ w_proj^T  (M=8192, N=1024, K=1024) -- tf32 mma
    gemm_tf32_nt<<<dim3(CDIM / 128, MTOT / 128), blk>>>(attn, w_proj, out, MTOT, CDIM, CDIM);
}

// round 11
// speedup vs baseline: 5.5878x; 1.1022x over previous
#include <cuda_runtime.h>
#include <cuda_bf16.h>
#include <cstdint>

// Problem constants
#define BQ    4
#define TSEQ  2048
#define CDIM  1024
#define NH    16
#define HD    64
#define MTOT  (BQ * TSEQ)          // 8192 rows
#define QKVF  (3 * CDIM)           // 3072

// Scratch (device globals: no runtime allocation allowed)
__device__ float g_qkv[(size_t)MTOT * QKVF];   // 96 MB
__device__ float g_attn[(size_t)MTOT * CDIM];  // 32 MB

__device__ __forceinline__ uint32_t f2tf(float f) {
    uint32_t u;
    asm("cvt.rna.tf32.f32 %0, %1;" : "=r"(u) : "f"(f));
    return u;
}

// ---------------------------------------------------------------------------
// TF32 tensor-core GEMM (NT): C[m,n] = sum_k A[m,k] * B[n,k]
// A: [M,K] row-major, B: [N,K] row-major, C: [M,N] row-major.
// 128x128x16 block tiles, 128 threads = 4 warps (2x2), warp tile 64x64 as
// 4x8 mma.sync.m16n8k8 tiles. fp32 accumulation.
// LDS words per mma = 1.0 (was 1.5 with 32x64 warp tiles) -> less crossbar
// pressure, which R7 ncu showed as the binding resource (L1=71%, tensor=39%).
// Smem rows stride 20 words: fragment LDS conflict-free (banks 20r+c mod 32
// tile all 32), STS.128 at worst 2-way.
// ---------------------------------------------------------------------------
#define SSTRIDE 20

__global__ __launch_bounds__(128) void gemm_tf32_nt(const float* __restrict__ A,
                                                    const float* __restrict__ B,
                                                    float* __restrict__ C,
                                                    int M, int N, int K)
{
    __shared__ __align__(16) uint32_t As[2][128 * SSTRIDE];
    __shared__ __align__(16) uint32_t Bs[2][128 * SSTRIDE];

    const int tid  = threadIdx.x;
    const int bm   = blockIdx.y * 128;
    const int bn   = blockIdx.x * 128;
    const int warp = tid >> 5;
    const int lane = tid & 31;
    const int r    = lane >> 2;      // fragment row group 0..7
    const int c    = lane & 3;       // fragment col group 0..3
    const int wm   = (warp >> 1) * 64;
    const int wn   = (warp & 1) * 64;

    // Loader mapping: 128 threads, float4 along k; rows lr, +32, +64, +96
    const int lr = tid >> 2;         // 0..31
    const int ls = (tid & 3) * 4;    // k offset

    const float* Ap[4];
    const float* Bp[4];
#pragma unroll
    for (int q = 0; q < 4; q++) {
        Ap[q] = A + (size_t)(bm + lr + q * 32) * K + ls;
        Bp[q] = B + (size_t)(bn + lr + q * 32) * K + ls;
    }

    float acc[4][8][4];
#pragma unroll
    for (int mi = 0; mi < 4; mi++)
#pragma unroll
        for (int ni = 0; ni < 8; ni++)
#pragma unroll
            for (int e = 0; e < 4; e++) acc[mi][ni][e] = 0.f;

    auto stash = [&](int buf, const float4* va, const float4* vb) {
#pragma unroll
        for (int q = 0; q < 4; q++) {
            uint4 u;
            u.x = f2tf(va[q].x); u.y = f2tf(va[q].y);
            u.z = f2tf(va[q].z); u.w = f2tf(va[q].w);
            *(uint4*)&As[buf][(lr + q * 32) * SSTRIDE + ls] = u;
            u.x = f2tf(vb[q].x); u.y = f2tf(vb[q].y);
            u.z = f2tf(vb[q].z); u.w = f2tf(vb[q].w);
            *(uint4*)&Bs[buf][(lr + q * 32) * SSTRIDE + ls] = u;
        }
    };

    // Prologue: tile 0 into buffer 0
    {
        float4 va[4], vb[4];
#pragma unroll
        for (int q = 0; q < 4; q++) {
            va[q] = *(const float4*)(Ap[q]);
            vb[q] = *(const float4*)(Bp[q]);
        }
        stash(0, va, vb);
    }
    __syncthreads();

    const int NT = K / 16;
    int p = 0;
    for (int kt = 0; kt < NT; kt++) {
        float4 na[4], nb[4];
        const bool has_next = (kt + 1 < NT);
        if (has_next) {
            const int off = (kt + 1) * 16;
#pragma unroll
            for (int q = 0; q < 4; q++) {
                na[q] = *(const float4*)(Ap[q] + off);
                nb[q] = *(const float4*)(Bp[q] + off);
            }
        }

        // Compute on buffer p
#pragma unroll
        for (int ks = 0; ks < 16; ks += 8) {
            uint32_t af[4][4];
#pragma unroll
            for (int mi = 0; mi < 4; mi++) {
                const uint32_t* base = &As[p][(wm + mi * 16 + r) * SSTRIDE];
                af[mi][0] = base[ks + c];
                af[mi][1] = base[8 * SSTRIDE + ks + c];
                af[mi][2] = base[ks + c + 4];
                af[mi][3] = base[8 * SSTRIDE + ks + c + 4];
            }
            uint32_t bf[8][2];
#pragma unroll
            for (int ni = 0; ni < 8; ni++) {
                const uint32_t* base = &Bs[p][(wn + ni * 8 + r) * SSTRIDE];
                bf[ni][0] = base[ks + c];
                bf[ni][1] = base[ks + c + 4];
            }
#pragma unroll
            for (int mi = 0; mi < 4; mi++)
#pragma unroll
                for (int ni = 0; ni < 8; ni++) {
                    float* d = acc[mi][ni];
                    asm volatile(
                        "mma.sync.aligned.m16n8k8.row.col.f32.tf32.tf32.f32 "
                        "{%0,%1,%2,%3}, {%4,%5,%6,%7}, {%8,%9}, {%0,%1,%2,%3};"
                        : "+f"(d[0]), "+f"(d[1]), "+f"(d[2]), "+f"(d[3])
                        : "r"(af[mi][0]), "r"(af[mi][1]), "r"(af[mi][2]), "r"(af[mi][3]),
                          "r"(bf[ni][0]), "r"(bf[ni][1]));
                }
        }

        if (has_next) {
            stash(p ^ 1, na, nb);
            __syncthreads();
            p ^= 1;
        }
    }

    // Epilogue: fragment (row, 2c) / (row+8, 2c) float2 stores
#pragma unroll
    for (int mi = 0; mi < 4; mi++) {
        const int row0 = bm + wm + mi * 16 + r;
#pragma unroll
        for (int ni = 0; ni < 8; ni++) {
            const int col = bn + wn + ni * 8 + 2 * c;
            float* d = acc[mi][ni];
            *(float2*)&C[(size_t)row0 * N + col]       = make_float2(d[0], d[1]);
            *(float2*)&C[(size_t)(row0 + 8) * N + col] = make_float2(d[2], d[3]);
        }
    }
}

// ---------------------------------------------------------------------------
// Tensor-core flash attention (tf32 mma, fp32 accum, causal).
// Block: 128 q-rows, 8 warps (16 rows each). K/V tiles 64 x 64.
// Q fragments + O accumulators + softmax stats fully register-resident.
// Reversed qt scheduling: heavy (late) q-tiles launch first.
// ---------------------------------------------------------------------------
#define KSTR 68
#define VSTR 72
#define PSTR 68
#define ATT_SMEM_WORDS (64 * KSTR + 64 * VSTR + 128 * PSTR)
#define ATT_SMEM_BYTES (ATT_SMEM_WORDS * 4)

__global__ __launch_bounds__(256, 2) void attn_tc(const float* __restrict__ qkv,
                                                  float* __restrict__ out)
{
    extern __shared__ uint32_t smu[];
    uint32_t* Ks = smu;
    uint32_t* Vs = Ks + 64 * KSTR;
    uint32_t* Ps = Vs + 64 * VSTR;

    const int tid  = threadIdx.x;
    const int warp = tid >> 5;
    const int lane = tid & 31;
    const int r    = lane >> 2;
    const int c    = lane & 3;
    const int qt   = (int)gridDim.x - 1 - (int)blockIdx.x;   // heavy tiles first
    const int bh   = blockIdx.y;
    const int b    = bh >> 4;
    const int h    = bh & 15;
    const int wrow = warp * 16;
    const size_t base = (size_t)b * TSEQ;

#pragma unroll
    for (int it = 0; it < 8; it++) {
        int idx = tid + it * 256;
        int row = idx >> 4;
        int d4  = idx & 15;
        float4 v = *(const float4*)(qkv + (base + qt * 128 + row) * (size_t)QKVF
                                    + h * HD + d4 * 4);
        uint4 u;
        u.x = __float_as_uint(v.x * 0.125f);
        u.y = __float_as_uint(v.y * 0.125f);
        u.z = __float_as_uint(v.z * 0.125f);
        u.w = __float_as_uint(v.w * 0.125f);
        *(uint4*)&Ps[row * PSTR + d4 * 4] = u;
    }
    __syncthreads();

    uint32_t qf[8][4];
#pragma unroll
    for (int k0 = 0; k0 < 8; k0++) {
        const uint32_t* bq = &Ps[(wrow + r) * PSTR + k0 * 8];
        qf[k0][0] = f2tf(__uint_as_float(bq[c]));
        qf[k0][1] = f2tf(__uint_as_float(bq[8 * PSTR + c]));
        qf[k0][2] = f2tf(__uint_as_float(bq[c + 4]));
        qf[k0][3] = f2tf(__uint_as_float(bq[8 * PSTR + c + 4]));
    }

    float o[8][4];
#pragma unroll
    for (int ni = 0; ni < 8; ni++)
#pragma unroll
        for (int e = 0; e < 4; e++) o[ni][e] = 0.f;
    float m0 = -1e30f, m1 = -1e30f, l0 = 0.f, l1 = 0.f;

    const int ktmax = 2 * qt + 1;
    for (int kt = 0; kt <= ktmax; kt++) {
        __syncthreads();

#pragma unroll
        for (int it = 0; it < 4; it++) {
            int idx = tid + it * 256;
            int row = idx >> 4;
            int d4  = idx & 15;
            const float* p = qkv + (base + kt * 64 + row) * (size_t)QKVF
                             + CDIM + h * HD + d4 * 4;
            float4 kv = *(const float4*)p;
            float4 vv = *(const float4*)(p + CDIM);
            uint4 u;
            u.x = f2tf(kv.x); u.y = f2tf(kv.y); u.z = f2tf(kv.z); u.w = f2tf(kv.w);
            *(uint4*)&Ks[row * KSTR + d4 * 4] = u;
            u.x = f2tf(vv.x); u.y = f2tf(vv.y); u.z = f2tf(vv.z); u.w = f2tf(vv.w);
            *(uint4*)&Vs[row * VSTR + d4 * 4] = u;
        }
        __syncthreads();

        float s[8][4];
#pragma unroll
        for (int ni = 0; ni < 8; ni++)
#pragma unroll
            for (int e = 0; e < 4; e++) s[ni][e] = 0.f;

#pragma unroll
        for (int k0 = 0; k0 < 8; k0++) {
#pragma unroll
            for (int ni = 0; ni < 8; ni++) {
                const uint32_t* bk = &Ks[(ni * 8 + r) * KSTR + k0 * 8];
                uint32_t b0 = bk[c];
                uint32_t b1 = bk[c + 4];
                float* d = s[ni];
                asm volatile(
                    "mma.sync.aligned.m16n8k8.row.col.f32.tf32.tf32.f32 "
                    "{%0,%1,%2,%3}, {%4,%5,%6,%7}, {%8,%9}, {%0,%1,%2,%3};"
                    : "+f"(d[0]), "+f"(d[1]), "+f"(d[2]), "+f"(d[3])
                    : "r"(qf[k0][0]), "r"(qf[k0][1]), "r"(qf[k0][2]), "r"(qf[k0][3]),
                      "r"(b0), "r"(b1));
            }
        }

        if (kt >= 2 * qt) {
            const int row0 = qt * 128 + wrow + r;
#pragma unroll
            for (int ni = 0; ni < 8; ni++) {
                int col = kt * 64 + ni * 8 + 2 * c;
                if (col     > row0)     s[ni][0] = -1e30f;
                if (col + 1 > row0)     s[ni][1] = -1e30f;
                if (col     > row0 + 8) s[ni][2] = -1e30f;
                if (col + 1 > row0 + 8) s[ni][3] = -1e30f;
            }
        }

        float mx0 = -1e30f, mx1 = -1e30f;
#pragma unroll
        for (int ni = 0; ni < 8; ni++) {
            mx0 = fmaxf(mx0, fmaxf(s[ni][0], s[ni][1]));
            mx1 = fmaxf(mx1, fmaxf(s[ni][2], s[ni][3]));
        }
        mx0 = fmaxf(mx0, __shfl_xor_sync(0xffffffffu, mx0, 1));
        mx0 = fmaxf(mx0, __shfl_xor_sync(0xffffffffu, mx0, 2));
        mx1 = fmaxf(mx1, __shfl_xor_sync(0xffffffffu, mx1, 1));
        mx1 = fmaxf(mx1, __shfl_xor_sync(0xffffffffu, mx1, 2));

        float mn0 = fmaxf(m0, mx0);
        float mn1 = fmaxf(m1, mx1);
        float a0 = __expf(m0 - mn0);
        float a1 = __expf(m1 - mn1);
        m0 = mn0; m1 = mn1;

        float sum0 = 0.f, sum1 = 0.f;
#pragma unroll
        for (int ni = 0; ni < 8; ni++) {
            s[ni][0] = __expf(s[ni][0] - mn0);
            s[ni][1] = __expf(s[ni][1] - mn0);
            s[ni][2] = __expf(s[ni][2] - mn1);
            s[ni][3] = __expf(s[ni][3] - mn1);
            sum0 += s[ni][0] + s[ni][1];
            sum1 += s[ni][2] + s[ni][3];
        }
        sum0 += __shfl_xor_sync(0xffffffffu, sum0, 1);
        sum0 += __shfl_xor_sync(0xffffffffu, sum0, 2);
        sum1 += __shfl_xor_sync(0xffffffffu, sum1, 1);
        sum1 += __shfl_xor_sync(0xffffffffu, sum1, 2);
        l0 = l0 * a0 + sum0;
        l1 = l1 * a1 + sum1;

#pragma unroll
        for (int ni = 0; ni < 8; ni++) {
            o[ni][0] *= a0; o[ni][1] *= a0;
            o[ni][2] *= a1; o[ni][3] *= a1;
        }

#pragma unroll
        for (int ni = 0; ni < 8; ni++) {
            uint2 u;
            u.x = f2tf(s[ni][0]); u.y = f2tf(s[ni][1]);
            *(uint2*)&Ps[(wrow + r) * PSTR + ni * 8 + 2 * c] = u;
            u.x = f2tf(s[ni][2]); u.y = f2tf(s[ni][3]);
            *(uint2*)&Ps[(wrow + r + 8) * PSTR + ni * 8 + 2 * c] = u;
        }
        __syncwarp();

#pragma unroll
        for (int k0 = 0; k0 < 8; k0++) {
            const uint32_t* pb = &Ps[(wrow + r) * PSTR + k0 * 8];
            uint32_t pa0 = pb[c];
            uint32_t pa1 = pb[8 * PSTR + c];
            uint32_t pa2 = pb[c + 4];
            uint32_t pa3 = pb[8 * PSTR + c + 4];
#pragma unroll
            for (int ni = 0; ni < 8; ni++) {
                uint32_t b0 = Vs[(k0 * 8 + c) * VSTR + ni * 8 + r];
                uint32_t b1 = Vs[(k0 * 8 + c + 4) * VSTR + ni * 8 + r];
                float* d = o[ni];
                asm volatile(
                    "mma.sync.aligned.m16n8k8.row.col.f32.tf32.tf32.f32 "
                    "{%0,%1,%2,%3}, {%4,%5,%6,%7}, {%8,%9}, {%0,%1,%2,%3};"
                    : "+f"(d[0]), "+f"(d[1]), "+f"(d[2]), "+f"(d[3])
                    : "r"(pa0), "r"(pa1), "r"(pa2), "r"(pa3),
                      "r"(b0), "r"(b1));
            }
        }
    }

    const float inv0 = 1.0f / l0;
    const float inv1 = 1.0f / l1;
    const size_t row0 = base + qt * 128 + wrow + r;
#pragma unroll
    for (int ni = 0; ni < 8; ni++) {
        const int col = h * HD + ni * 8 + 2 * c;
        *(float2*)&out[row0 * CDIM + col] =
            make_float2(o[ni][0] * inv0, o[ni][1] * inv0);
        *(float2*)&out[(row0 + 8) * CDIM + col] =
            make_float2(o[ni][2] * inv1, o[ni][3] * inv1);
    }
}

// ---------------------------------------------------------------------------
extern "C" void kernel_launch(void* const* d_in, const int* in_sizes, int n_in,
                              void* d_out, int out_size)
{
    const float* x      = (const float*)d_in[0];
    const float* w_qkv  = (const float*)d_in[1];
    const float* w_proj = (const float*)d_in[2];
    float* out = (float*)d_out;

    float* qkv  = nullptr;
    float* attn = nullptr;
    cudaGetSymbolAddress((void**)&qkv,  g_qkv);
    cudaGetSymbolAddress((void**)&attn, g_attn);

    cudaFuncSetAttribute(attn_tc,
                         cudaFuncAttributeMaxDynamicSharedMemorySize,
                         ATT_SMEM_BYTES);

    // 1) QKV = x @ w_qkv^T   (M=8192, N=3072, K=1024)  -- tf32 mma, 64x64 warp tiles
    gemm_tf32_nt<<<dim3(QKVF / 128, MTOT / 128), 128>>>(x, w_qkv, qkv, MTOT, QKVF, CDIM);
    // 2) attention -- tf32 mma flash attention (heavy tiles first)
    attn_tc<<<dim3(TSEQ / 128, BQ * NH), 256, ATT_SMEM_BYTES>>>(qkv, attn);
    // 3) out = attn @ w_proj^T  (M=8192, N=1024, K=1024) -- tf32 mma
    gemm_tf32_nt<<<dim3(CDIM / 128, MTOT / 128), 128>>>(attn, w_proj, out, MTOT, CDIM, CDIM);
}